// round 1
// baseline (speedup 1.0000x reference)
#include <cuda_runtime.h>
#include <math.h>

#define BATCH 4
#define NPTS 4096
#define NPTS2 4096
#define CINC 128
#define DIMC 64
#define KNNC 20
#define UPF 2
#define HPOSC 64
#define HATTC 256
#define EPSV 1e-5f

// ---------------- scratch (static device memory; no allocations) ----------------
__device__ float g_qt[BATCH * NPTS * DIMC];   // (b, n, o) point-major
__device__ float g_kt[BATCH * NPTS2 * DIMC];
__device__ float g_vt[BATCH * NPTS2 * DIMC];
__device__ int   g_idx[BATCH * NPTS * KNNC];

// ================= QKV projection kernel =================
// grid (N/64, B), block 256. Computes q,k,v into point-major scratch.
__global__ __launch_bounds__(256) void qkv_kernel(
    const float* __restrict__ query, const float* __restrict__ key_feat,
    const float* __restrict__ wq, const float* __restrict__ bq,
    const float* __restrict__ wk, const float* __restrict__ bk,
    const float* __restrict__ wv, const float* __restrict__ bv)
{
    int b = blockIdx.y;
    int n0 = blockIdx.x * 64;
    int tid = threadIdx.x;
    __shared__ float tile[CINC * 64];

    // ---- q from query ----
    for (int i = tid; i < CINC * 64; i += 256) {
        int c = i >> 6, j = i & 63;
        tile[i] = query[(b * CINC + c) * NPTS + n0 + j];
    }
    __syncthreads();
    int o = tid & 63;
    int jb = tid >> 6;  // 0..3
    {
        float acc[16];
#pragma unroll
        for (int i = 0; i < 16; i++) acc[i] = 0.f;
        for (int c = 0; c < CINC; c++) {
            float w = wq[o * CINC + c];
#pragma unroll
            for (int i = 0; i < 16; i++)
                acc[i] = fmaf(w, tile[c * 64 + jb + 4 * i], acc[i]);
        }
        float bias = bq[o];
#pragma unroll
        for (int i = 0; i < 16; i++)
            g_qt[(b * NPTS + n0 + jb + 4 * i) * DIMC + o] = acc[i] + bias;
    }
    __syncthreads();
    // ---- k, v from key_feat ----
    for (int i = tid; i < CINC * 64; i += 256) {
        int c = i >> 6, j = i & 63;
        tile[i] = key_feat[(b * CINC + c) * NPTS2 + n0 + j];
    }
    __syncthreads();
    {
        float acck[16], accv[16];
#pragma unroll
        for (int i = 0; i < 16; i++) { acck[i] = 0.f; accv[i] = 0.f; }
        for (int c = 0; c < CINC; c++) {
            float wkk = wk[o * CINC + c];
            float wvv = wv[o * CINC + c];
#pragma unroll
            for (int i = 0; i < 16; i++) {
                float t = tile[c * 64 + jb + 4 * i];
                acck[i] = fmaf(wkk, t, acck[i]);
                accv[i] = fmaf(wvv, t, accv[i]);
            }
        }
        float bkk = bk[o], bvv = bv[o];
#pragma unroll
        for (int i = 0; i < 16; i++) {
            int nn = n0 + jb + 4 * i;
            g_kt[(b * NPTS2 + nn) * DIMC + o] = acck[i] + bkk;
            g_vt[(b * NPTS2 + nn) * DIMC + o] = accv[i] + bvv;
        }
    }
}

// ================= KNN kernel =================
// grid (N/256, B), block 256. One thread per query point; support set staged in smem.
__global__ __launch_bounds__(256) void knn_kernel(
    const float* __restrict__ pos1, const float* __restrict__ pos2)
{
    int b = blockIdx.y;
    int tid = threadIdx.x;
    int n = blockIdx.x * 256 + tid;
    __shared__ float sx[2048], sy[2048], sz[2048], sn[2048];

    float qx = pos1[(b * 3 + 0) * NPTS + n];
    float qy = pos1[(b * 3 + 1) * NPTS + n];
    float qz = pos1[(b * 3 + 2) * NPTS + n];
    float n1 = qx * qx + qy * qy + qz * qz;

    float bd[KNNC];
    int bi[KNNC];
#pragma unroll
    for (int j = 0; j < KNNC; j++) { bd[j] = 3.4e38f; bi[j] = 0; }

    for (int chunk = 0; chunk < 2; chunk++) {
        int base = chunk * 2048;
        __syncthreads();
        for (int i = tid; i < 2048; i += 256) {
            float x = pos2[(b * 3 + 0) * NPTS2 + base + i];
            float y = pos2[(b * 3 + 1) * NPTS2 + base + i];
            float z = pos2[(b * 3 + 2) * NPTS2 + base + i];
            sx[i] = x; sy[i] = y; sz[i] = z;
            sn[i] = x * x + y * y + z * z;
        }
        __syncthreads();
#pragma unroll 4
        for (int m = 0; m < 2048; m++) {
            float dot = fmaf(qx, sx[m], fmaf(qy, sy[m], qz * sz[m]));
            float d = n1 + sn[m] - 2.f * dot;
            if (d < bd[KNNC - 1]) {
                float cd = d; int ci = base + m;
#pragma unroll
                for (int j = 0; j < KNNC; j++) {
                    if (cd < bd[j]) {
                        float td = bd[j]; bd[j] = cd; cd = td;
                        int ti = bi[j]; bi[j] = ci; ci = ti;
                    }
                }
            }
        }
    }
#pragma unroll
    for (int j = 0; j < KNNC; j++) g_idx[(n + b * NPTS) * KNNC + j] = bi[j];
}

// ================= Fused per-point attention kernel =================
// grid (N, B), block 256. One block per output point.
__global__ __launch_bounds__(256) void attn_kernel(
    const float* __restrict__ pos1, const float* __restrict__ pos2,
    const float* __restrict__ query,
    const float* __restrict__ pw1, const float* __restrict__ pb1,
    const float* __restrict__ pg,  const float* __restrict__ pbt,
    const float* __restrict__ pm,  const float* __restrict__ pv,
    const float* __restrict__ pw2, const float* __restrict__ pb2,
    const float* __restrict__ aw1, const float* __restrict__ ab1,
    const float* __restrict__ ag,  const float* __restrict__ abt2,
    const float* __restrict__ am,  const float* __restrict__ av,
    const float* __restrict__ awt, const float* __restrict__ abt,
    const float* __restrict__ we,  const float* __restrict__ be,
    float* __restrict__ out)
{
    int b = blockIdx.y;
    int n = blockIdx.x;
    int tid = threadIdx.x;

    __shared__ __align__(16) float s_h[DIMC * KNNC];     // q - kg + pe
    __shared__ __align__(16) float s_vg[DIMC * KNNC];    // v gathered + pe
    __shared__ __align__(16) float s_a[HATTC * KNNC];    // attn mlp hidden
    __shared__ __align__(16) float s_buf[128 * KNNC];    // pe1 / att partial
    __shared__ float s_q[DIMC];
    __shared__ float s_prel[3 * KNNC];
    __shared__ float s_agg[DIMC * UPF];
    __shared__ int   s_idx[KNNC];

    // ---- Phase 0: load idx, q ----
    if (tid < KNNC) s_idx[tid] = g_idx[(b * NPTS + n) * KNNC + tid];
    if (tid < DIMC) s_q[tid] = g_qt[(b * NPTS + n) * DIMC + tid];
    __syncthreads();

    // pos_rel and gathers
    if (tid < 3 * KNNC) {
        int c = tid / KNNC, k = tid - c * KNNC;
        s_prel[tid] = pos1[(b * 3 + c) * NPTS + n] - pos2[(b * 3 + c) * NPTS2 + s_idx[k]];
    }
    for (int e = tid; e < DIMC * KNNC; e += 256) {
        int k = e >> 6, o = e & 63;
        int m = s_idx[k];
        s_h[o * KNNC + k]  = s_q[o] - g_kt[(b * NPTS2 + m) * DIMC + o];
        s_vg[o * KNNC + k] = g_vt[(b * NPTS2 + m) * DIMC + o];
    }
    __syncthreads();

    // ---- Phase 1: pos mlp layer 1 (3->64) + BN + ReLU into s_buf ----
    for (int e = tid; e < HPOSC * KNNC; e += 256) {
        int h = e / KNNC, k = e - h * KNNC;
        float acc = fmaf(pw1[h * 3 + 0], s_prel[k],
                    fmaf(pw1[h * 3 + 1], s_prel[KNNC + k],
                         pw1[h * 3 + 2] * s_prel[2 * KNNC + k])) + pb1[h];
        float inv = pg[h] / sqrtf(pv[h] + EPSV);
        acc = fmaf(acc, inv, pbt[h] - pm[h] * inv);
        s_buf[h * KNNC + k] = fmaxf(acc, 0.f);
    }
    __syncthreads();

    // ---- Phase 1b: pos mlp layer 2 (64->64); add pe into h and vg ----
    for (int e = tid; e < DIMC * KNNC; e += 256) {
        int o = e / KNNC, k = e - o * KNNC;
        float acc = pb2[o];
#pragma unroll 8
        for (int h = 0; h < HPOSC; h++)
            acc = fmaf(pw2[o * HPOSC + h], s_buf[h * KNNC + k], acc);
        s_h[o * KNNC + k]  += acc;
        s_vg[o * KNNC + k] += acc;
    }
    __syncthreads();

    // ---- Phase 2: a = relu(bn(aw1 @ h)) : 256 x 20, inner 64 ----
    {
        int c = tid;  // 0..255
        float inv = ag[c] / sqrtf(av[c] + EPSV);
        float bias = fmaf(ab1[c], inv, abt2[c]) - am[c] * inv;
        float acc[KNNC];
#pragma unroll
        for (int k = 0; k < KNNC; k++) acc[k] = 0.f;
        const float4* w4 = reinterpret_cast<const float4*>(aw1 + c * DIMC);
#pragma unroll 4
        for (int oq = 0; oq < DIMC / 4; oq++) {
            float4 w = w4[oq];
#pragma unroll
            for (int j = 0; j < 4; j++) {
                float wj = (j == 0) ? w.x : (j == 1) ? w.y : (j == 2) ? w.z : w.w;
                const float4* hh = reinterpret_cast<const float4*>(s_h + (oq * 4 + j) * KNNC);
#pragma unroll
                for (int kq = 0; kq < KNNC / 4; kq++) {
                    float4 hv = hh[kq];
                    acc[4 * kq + 0] = fmaf(wj, hv.x, acc[4 * kq + 0]);
                    acc[4 * kq + 1] = fmaf(wj, hv.y, acc[4 * kq + 1]);
                    acc[4 * kq + 2] = fmaf(wj, hv.z, acc[4 * kq + 2]);
                    acc[4 * kq + 3] = fmaf(wj, hv.w, acc[4 * kq + 3]);
                }
            }
        }
#pragma unroll
        for (int k = 0; k < KNNC; k++)
            s_a[c * KNNC + k] = fmaxf(fmaf(acc[k], inv, bias), 0.f);
    }
    __syncthreads();

    // ---- Phase 3: att = awt^T @ a : rows (o,r)=128, inner 256 split across 2 thread halves ----
    int row = tid & 127;         // = o*2 + r
    int chalf = tid >> 7;        // which half of the 256 channels
    float acc3[KNNC];
    {
#pragma unroll
        for (int k = 0; k < KNNC; k++) acc3[k] = 0.f;
        const float* wbase = awt + (chalf * 128) * (DIMC * UPF) + row;
#pragma unroll 4
        for (int cc = 0; cc < 128; cc++) {
            float w = wbase[cc * (DIMC * UPF)];
            const float4* aa = reinterpret_cast<const float4*>(s_a + (chalf * 128 + cc) * KNNC);
#pragma unroll
            for (int kq = 0; kq < KNNC / 4; kq++) {
                float4 v4 = aa[kq];
                acc3[4 * kq + 0] = fmaf(w, v4.x, acc3[4 * kq + 0]);
                acc3[4 * kq + 1] = fmaf(w, v4.y, acc3[4 * kq + 1]);
                acc3[4 * kq + 2] = fmaf(w, v4.z, acc3[4 * kq + 2]);
                acc3[4 * kq + 3] = fmaf(w, v4.w, acc3[4 * kq + 3]);
            }
        }
        if (chalf) {
#pragma unroll
            for (int k = 0; k < KNNC; k++) s_buf[row * KNNC + k] = acc3[k];
        }
    }
    __syncthreads();

    // ---- Phase 4: combine halves, softmax over K, weighted sum with vg ----
    if (tid < 128) {
        int o = row >> 1;
        float ab = abt[o];
        float vals[KNNC];
        float mx = -3.4e38f;
#pragma unroll
        for (int k = 0; k < KNNC; k++) {
            float t = acc3[k] + s_buf[row * KNNC + k] + ab;
            vals[k] = t;
            mx = fmaxf(mx, t);
        }
        float s = 0.f, wsum = 0.f;
#pragma unroll
        for (int k = 0; k < KNNC; k++) {
            float e = expf(vals[k] - mx);
            s += e;
            wsum = fmaf(e, s_vg[o * KNNC + k], wsum);
        }
        s_agg[row] = wsum / s;   // row = o*2 + r
    }
    __syncthreads();

    // ---- Phase 5: y = we @ agg + be + residual ----
    {
        int c2 = tid >> 1, r = tid & 1;
        float acc = 0.f;
#pragma unroll
        for (int o = 0; o < DIMC; o++)
            acc = fmaf(we[c2 * DIMC + o], s_agg[o * UPF + r], acc);
        out[((size_t)(b * CINC + c2)) * (NPTS * UPF) + 2 * (size_t)n + r] =
            acc + be[c2] + query[(b * CINC + c2) * NPTS + n];
    }
}

// ================= launch =================
extern "C" void kernel_launch(void* const* d_in, const int* in_sizes, int n_in,
                              void* d_out, int out_size)
{
    const float* pos1     = (const float*)d_in[0];
    const float* query    = (const float*)d_in[1];
    const float* pos2     = (const float*)d_in[2];
    const float* key_feat = (const float*)d_in[3];
    const float* wq  = (const float*)d_in[4];
    const float* bq  = (const float*)d_in[5];
    const float* wk  = (const float*)d_in[6];
    const float* bk  = (const float*)d_in[7];
    const float* wv  = (const float*)d_in[8];
    const float* bv  = (const float*)d_in[9];
    const float* pw1 = (const float*)d_in[10];
    const float* pb1 = (const float*)d_in[11];
    const float* pg  = (const float*)d_in[12];
    const float* pbt = (const float*)d_in[13];
    const float* pm  = (const float*)d_in[14];
    const float* pv  = (const float*)d_in[15];
    const float* pw2 = (const float*)d_in[16];
    const float* pb2 = (const float*)d_in[17];
    const float* aw1 = (const float*)d_in[18];
    const float* ab1 = (const float*)d_in[19];
    const float* ag  = (const float*)d_in[20];
    const float* abt2= (const float*)d_in[21];
    const float* am  = (const float*)d_in[22];
    const float* av  = (const float*)d_in[23];
    const float* awt = (const float*)d_in[24];
    const float* abt = (const float*)d_in[25];
    const float* we  = (const float*)d_in[26];
    const float* be  = (const float*)d_in[27];
    float* out = (float*)d_out;

    qkv_kernel<<<dim3(NPTS / 64, BATCH), 256>>>(query, key_feat, wq, bq, wk, bk, wv, bv);
    knn_kernel<<<dim3(NPTS / 256, BATCH), 256>>>(pos1, pos2);
    attn_kernel<<<dim3(NPTS, BATCH), 256>>>(
        pos1, pos2, query,
        pw1, pb1, pg, pbt, pm, pv, pw2, pb2,
        aw1, ab1, ag, abt2, am, av, awt, abt, we, be, out);
}

// round 2
// speedup vs baseline: 1.2201x; 1.2201x over previous
#include <cuda_runtime.h>
#include <math.h>

#define BATCH 4
#define NPTS 4096
#define NPTS2 4096
#define CINC 128
#define DIMC 64
#define KNNC 20
#define UPF 2
#define HPOSC 64
#define HATTC 256
#define EPSV 1e-5f

// ---------------- scratch (static device memory; no allocations) ----------------
__device__ float g_qt[BATCH * NPTS * DIMC];   // (b, n, o) point-major
__device__ float g_kt[BATCH * NPTS2 * DIMC];
__device__ float g_vt[BATCH * NPTS2 * DIMC];
__device__ int   g_idx[BATCH * NPTS * KNNC];
__device__ float g_aw1t[DIMC * HATTC];        // aw1 transposed: [o][c]
__device__ float g_pw2t[HPOSC * DIMC];        // pw2 transposed: [h][o]

// ---------------- packed f32x2 helpers ----------------
__device__ __forceinline__ unsigned long long ffma2(
    unsigned long long a, unsigned long long b, unsigned long long c) {
    unsigned long long d;
    asm("fma.rn.f32x2 %0, %1, %2, %3;" : "=l"(d) : "l"(a), "l"(b), "l"(c));
    return d;
}
__device__ __forceinline__ unsigned long long pack2(float lo, float hi) {
    unsigned long long d;
    asm("mov.b64 %0, {%1, %2};" : "=l"(d) : "f"(lo), "f"(hi));
    return d;
}
__device__ __forceinline__ void unpack2(unsigned long long v, float& lo, float& hi) {
    asm("mov.b64 {%0, %1}, %2;" : "=f"(lo), "=f"(hi) : "l"(v));
}

// ================= prep: transpose small weights =================
__global__ __launch_bounds__(256) void prep_kernel(
    const float* __restrict__ aw1, const float* __restrict__ pw2)
{
    int i = blockIdx.x * 256 + threadIdx.x;
    if (i < HATTC * DIMC) {            // aw1[c][o] -> g_aw1t[o][c]
        int c = i >> 6, o = i & 63;
        g_aw1t[o * HATTC + c] = aw1[i];
    }
    if (i < DIMC * HPOSC) {            // pw2[o][h] -> g_pw2t[h][o]
        int o = i >> 6, h = i & 63;
        g_pw2t[h * DIMC + o] = pw2[i];
    }
}

// ================= QKV projection kernel =================
__global__ __launch_bounds__(256) void qkv_kernel(
    const float* __restrict__ query, const float* __restrict__ key_feat,
    const float* __restrict__ wq, const float* __restrict__ bq,
    const float* __restrict__ wk, const float* __restrict__ bk,
    const float* __restrict__ wv, const float* __restrict__ bv)
{
    int b = blockIdx.y;
    int n0 = blockIdx.x * 64;
    int tid = threadIdx.x;
    __shared__ float tile[CINC * 64];

    // ---- q from query ----
    for (int i = tid; i < CINC * 64; i += 256) {
        int c = i >> 6, j = i & 63;
        tile[i] = query[(b * CINC + c) * NPTS + n0 + j];
    }
    __syncthreads();
    int o = tid & 63;
    int jb = tid >> 6;  // 0..3
    {
        float acc[16];
#pragma unroll
        for (int i = 0; i < 16; i++) acc[i] = 0.f;
        const float4* w4 = reinterpret_cast<const float4*>(wq + o * CINC);
        for (int c4 = 0; c4 < CINC / 4; c4++) {
            float4 w = w4[c4];
#pragma unroll
            for (int j = 0; j < 4; j++) {
                float wj = (j == 0) ? w.x : (j == 1) ? w.y : (j == 2) ? w.z : w.w;
                const float* tp = tile + (c4 * 4 + j) * 64 + jb;
#pragma unroll
                for (int i = 0; i < 16; i++)
                    acc[i] = fmaf(wj, tp[4 * i], acc[i]);
            }
        }
        float bias = bq[o];
#pragma unroll
        for (int i = 0; i < 16; i++)
            g_qt[(b * NPTS + n0 + jb + 4 * i) * DIMC + o] = acc[i] + bias;
    }
    __syncthreads();
    // ---- k, v from key_feat ----
    for (int i = tid; i < CINC * 64; i += 256) {
        int c = i >> 6, j = i & 63;
        tile[i] = key_feat[(b * CINC + c) * NPTS2 + n0 + j];
    }
    __syncthreads();
    {
        float acck[16], accv[16];
#pragma unroll
        for (int i = 0; i < 16; i++) { acck[i] = 0.f; accv[i] = 0.f; }
        const float4* wk4 = reinterpret_cast<const float4*>(wk + o * CINC);
        const float4* wv4 = reinterpret_cast<const float4*>(wv + o * CINC);
        for (int c4 = 0; c4 < CINC / 4; c4++) {
            float4 wa = wk4[c4];
            float4 wb = wv4[c4];
#pragma unroll
            for (int j = 0; j < 4; j++) {
                float wkk = (j == 0) ? wa.x : (j == 1) ? wa.y : (j == 2) ? wa.z : wa.w;
                float wvv = (j == 0) ? wb.x : (j == 1) ? wb.y : (j == 2) ? wb.z : wb.w;
                const float* tp = tile + (c4 * 4 + j) * 64 + jb;
#pragma unroll
                for (int i = 0; i < 16; i++) {
                    float t = tp[4 * i];
                    acck[i] = fmaf(wkk, t, acck[i]);
                    accv[i] = fmaf(wvv, t, accv[i]);
                }
            }
        }
        float bkk = bk[o], bvv = bv[o];
#pragma unroll
        for (int i = 0; i < 16; i++) {
            int nn = n0 + jb + 4 * i;
            g_kt[(b * NPTS2 + nn) * DIMC + o] = acck[i] + bkk;
            g_vt[(b * NPTS2 + nn) * DIMC + o] = accv[i] + bvv;
        }
    }
}

// ================= KNN kernel =================
__global__ __launch_bounds__(256) void knn_kernel(
    const float* __restrict__ pos1, const float* __restrict__ pos2)
{
    int b = blockIdx.y;
    int tid = threadIdx.x;
    int n = blockIdx.x * 256 + tid;
    __shared__ float sx[2048], sy[2048], sz[2048], sn[2048];

    float qx = pos1[(b * 3 + 0) * NPTS + n];
    float qy = pos1[(b * 3 + 1) * NPTS + n];
    float qz = pos1[(b * 3 + 2) * NPTS + n];
    float n1 = qx * qx + qy * qy + qz * qz;

    float bd[KNNC];
    int bi[KNNC];
#pragma unroll
    for (int j = 0; j < KNNC; j++) { bd[j] = 3.4e38f; bi[j] = 0; }

    for (int chunk = 0; chunk < 2; chunk++) {
        int base = chunk * 2048;
        __syncthreads();
        for (int i = tid; i < 2048; i += 256) {
            float x = pos2[(b * 3 + 0) * NPTS2 + base + i];
            float y = pos2[(b * 3 + 1) * NPTS2 + base + i];
            float z = pos2[(b * 3 + 2) * NPTS2 + base + i];
            sx[i] = x; sy[i] = y; sz[i] = z;
            sn[i] = x * x + y * y + z * z;
        }
        __syncthreads();
#pragma unroll 4
        for (int m = 0; m < 2048; m++) {
            float dot = fmaf(qx, sx[m], fmaf(qy, sy[m], qz * sz[m]));
            float d = n1 + sn[m] - 2.f * dot;
            if (d < bd[KNNC - 1]) {
                float cd = d; int ci = base + m;
#pragma unroll
                for (int j = 0; j < KNNC; j++) {
                    if (cd < bd[j]) {
                        float td = bd[j]; bd[j] = cd; cd = td;
                        int ti = bi[j]; bi[j] = ci; ci = ti;
                    }
                }
            }
        }
    }
#pragma unroll
    for (int j = 0; j < KNNC; j++) g_idx[(n + b * NPTS) * KNNC + j] = bi[j];
}

// ================= Fused per-point attention kernel =================
// grid (N, B), block 256. One block per output point.
__global__ __launch_bounds__(256) void attn_kernel(
    const float* __restrict__ pos1, const float* __restrict__ pos2,
    const float* __restrict__ query,
    const float* __restrict__ pw1, const float* __restrict__ pb1,
    const float* __restrict__ pg,  const float* __restrict__ pbt,
    const float* __restrict__ pm,  const float* __restrict__ pv,
    const float* __restrict__ pb2,
    const float* __restrict__ ab1,
    const float* __restrict__ ag,  const float* __restrict__ abt2,
    const float* __restrict__ am,  const float* __restrict__ av,
    const float* __restrict__ awt, const float* __restrict__ abt,
    const float* __restrict__ we,  const float* __restrict__ be,
    float* __restrict__ out)
{
    int b = blockIdx.y;
    int n = blockIdx.x;
    int tid = threadIdx.x;

    __shared__ __align__(16) float s_h[DIMC * KNNC];      // q - kg + pe   (rows stride 20)
    __shared__ __align__(16) float s_vg[DIMC * KNNC];     // v gathered + pe
    __shared__ __align__(16) float s_a[HATTC * KNNC];     // attn mlp hidden (rows stride 20)
    __shared__ __align__(16) float s_buf[128 * 24];       // pe1 (padded 24) / att partial (stride 24)
    __shared__ float s_q[DIMC];
    __shared__ float s_prel[3 * KNNC];
    __shared__ float s_agg[DIMC * UPF];
    __shared__ int   s_idx[KNNC];

    // ---- Phase 0: load idx, q ----
    if (tid < KNNC) s_idx[tid] = g_idx[(b * NPTS + n) * KNNC + tid];
    if (tid < DIMC) s_q[tid] = g_qt[(b * NPTS + n) * DIMC + tid];
    __syncthreads();

    if (tid < 3 * KNNC) {
        int c = tid / KNNC, k = tid - c * KNNC;
        s_prel[tid] = pos1[(b * 3 + c) * NPTS + n] - pos2[(b * 3 + c) * NPTS2 + s_idx[k]];
    }
    for (int e = tid; e < DIMC * KNNC; e += 256) {
        int k = e >> 6, o = e & 63;
        int m = s_idx[k];
        s_h[o * KNNC + k]  = s_q[o] - g_kt[(b * NPTS2 + m) * DIMC + o];
        s_vg[o * KNNC + k] = g_vt[(b * NPTS2 + m) * DIMC + o];
    }
    __syncthreads();

    // ---- Phase 1: pos mlp layer 1 (3->64) + BN + ReLU into s_buf (k padded to 24) ----
    for (int e = tid; e < HPOSC * 24; e += 256) {
        int h = e / 24, k = e - h * 24;
        float val = 0.f;
        if (k < KNNC) {
            float acc = fmaf(pw1[h * 3 + 0], s_prel[k],
                        fmaf(pw1[h * 3 + 1], s_prel[KNNC + k],
                             pw1[h * 3 + 2] * s_prel[2 * KNNC + k])) + pb1[h];
            float inv = pg[h] * rsqrtf(pv[h] + EPSV);
            acc = fmaf(acc, inv, pbt[h] - pm[h] * inv);
            val = fmaxf(acc, 0.f);
        }
        s_buf[h * 24 + k] = val;
    }
    __syncthreads();

    // ---- Phase 1b: pos mlp layer 2 (64->64) via f32x2 over channel pairs ----
    {
        int op = tid & 31, kg = tid >> 5;   // op: o-pair, kg: 0..7 (3 k's each over padded 24)
        int o0 = op * 2, k0 = kg * 3;
        unsigned long long acc[3] = {0ULL, 0ULL, 0ULL};
#pragma unroll 4
        for (int h = 0; h < HPOSC; h++) {
            unsigned long long w2 =
                *reinterpret_cast<const unsigned long long*>(g_pw2t + h * DIMC + o0);
            const float* br = s_buf + h * 24 + k0;
            acc[0] = ffma2(w2, pack2(br[0], br[0]), acc[0]);
            acc[1] = ffma2(w2, pack2(br[1], br[1]), acc[1]);
            acc[2] = ffma2(w2, pack2(br[2], br[2]), acc[2]);
        }
        float b0 = pb2[o0], b1 = pb2[o0 + 1];
#pragma unroll
        for (int j = 0; j < 3; j++) {
            int k = k0 + j;
            if (k < KNNC) {
                float lo, hi;
                unpack2(acc[j], lo, hi);
                float v0 = lo + b0, v1 = hi + b1;
                s_h[o0 * KNNC + k] += v0;
                s_vg[o0 * KNNC + k] += v0;
                s_h[(o0 + 1) * KNNC + k] += v1;
                s_vg[(o0 + 1) * KNNC + k] += v1;
            }
        }
    }
    __syncthreads();

    // ---- Phase 2: a = relu(bn(aw1 @ h)), f32x2 over k pairs, 2 passes of 128 channels ----
    {
        int cp = tid & 127, half = tid >> 7;
        int obase = half * 32;
#pragma unroll
        for (int p = 0; p < 2; p++) {
            int c = cp + p * 128;
            unsigned long long acc[10];
#pragma unroll
            for (int j = 0; j < 10; j++) acc[j] = 0ULL;
#pragma unroll 4
            for (int oo = 0; oo < 32; oo++) {
                int o = obase + oo;
                float w = g_aw1t[o * HATTC + c];
                unsigned long long wp = pack2(w, w);
                const ulonglong2* hr = reinterpret_cast<const ulonglong2*>(s_h + o * KNNC);
#pragma unroll
                for (int j = 0; j < 5; j++) {
                    ulonglong2 hv = hr[j];
                    acc[2 * j]     = ffma2(wp, hv.x, acc[2 * j]);
                    acc[2 * j + 1] = ffma2(wp, hv.y, acc[2 * j + 1]);
                }
            }
            if (half) {
                unsigned long long* dst = reinterpret_cast<unsigned long long*>(s_a + c * KNNC);
#pragma unroll
                for (int j = 0; j < 10; j++) dst[j] = acc[j];
            }
            __syncthreads();
            if (!half) {
                float inv = ag[c] * rsqrtf(av[c] + EPSV);
                float bias = fmaf(ab1[c], inv, abt2[c]) - am[c] * inv;
                float* row = s_a + c * KNNC;
#pragma unroll
                for (int j = 0; j < 10; j++) {
                    float lo, hi;
                    unpack2(acc[j], lo, hi);
                    row[2 * j]     = fmaxf(fmaf(lo + row[2 * j],     inv, bias), 0.f);
                    row[2 * j + 1] = fmaxf(fmaf(hi + row[2 * j + 1], inv, bias), 0.f);
                }
            }
            __syncthreads();
        }
    }

    // ---- Phase 3: att partial = awt^T @ a, f32x2, rows 128, channel halves ----
    int row = tid & 127;
    int chalf = tid >> 7;
    unsigned long long acc3[10];
    {
#pragma unroll
        for (int j = 0; j < 10; j++) acc3[j] = 0ULL;
        const float* wb = awt + (chalf * 128) * (DIMC * UPF) + row;
#pragma unroll 8
        for (int cc = 0; cc < 128; cc++) {
            float w = wb[cc * (DIMC * UPF)];
            unsigned long long wp = pack2(w, w);
            const ulonglong2* ar =
                reinterpret_cast<const ulonglong2*>(s_a + (chalf * 128 + cc) * KNNC);
#pragma unroll
            for (int j = 0; j < 5; j++) {
                ulonglong2 av2 = ar[j];
                acc3[2 * j]     = ffma2(wp, av2.x, acc3[2 * j]);
                acc3[2 * j + 1] = ffma2(wp, av2.y, acc3[2 * j + 1]);
            }
        }
        if (chalf) {
            unsigned long long* dst = reinterpret_cast<unsigned long long*>(s_buf) + row * 12;
#pragma unroll
            for (int j = 0; j < 10; j++) dst[j] = acc3[j];
        }
    }
    __syncthreads();

    // ---- Phase 4: combine halves, softmax over K, weighted sum with vg ----
    if (tid < 128) {
        int o = row >> 1;
        float ab = abt[o];
        float vals[KNNC];
        float mx = -3.4e38f;
#pragma unroll
        for (int j = 0; j < 10; j++) {
            float lo, hi;
            unpack2(acc3[j], lo, hi);
            float t0 = lo + s_buf[row * 24 + 2 * j] + ab;
            float t1 = hi + s_buf[row * 24 + 2 * j + 1] + ab;
            vals[2 * j] = t0;
            vals[2 * j + 1] = t1;
            mx = fmaxf(mx, fmaxf(t0, t1));
        }
        float s = 0.f, wsum = 0.f;
#pragma unroll
        for (int k = 0; k < KNNC; k++) {
            float e = expf(vals[k] - mx);
            s += e;
            wsum = fmaf(e, s_vg[o * KNNC + k], wsum);
        }
        s_agg[row] = wsum / s;   // row = o*2 + r
    }
    __syncthreads();

    // ---- Phase 5: y = we @ agg + be + residual ----
    {
        int c2 = tid >> 1, r = tid & 1;
        float acc = 0.f;
#pragma unroll
        for (int o = 0; o < DIMC; o++)
            acc = fmaf(we[c2 * DIMC + o], s_agg[o * UPF + r], acc);
        out[((size_t)(b * CINC + c2)) * (NPTS * UPF) + 2 * (size_t)n + r] =
            acc + be[c2] + query[(b * CINC + c2) * NPTS + n];
    }
}

// ================= launch =================
extern "C" void kernel_launch(void* const* d_in, const int* in_sizes, int n_in,
                              void* d_out, int out_size)
{
    const float* pos1     = (const float*)d_in[0];
    const float* query    = (const float*)d_in[1];
    const float* pos2     = (const float*)d_in[2];
    const float* key_feat = (const float*)d_in[3];
    const float* wq  = (const float*)d_in[4];
    const float* bq  = (const float*)d_in[5];
    const float* wk  = (const float*)d_in[6];
    const float* bk  = (const float*)d_in[7];
    const float* wv  = (const float*)d_in[8];
    const float* bv  = (const float*)d_in[9];
    const float* pw1 = (const float*)d_in[10];
    const float* pb1 = (const float*)d_in[11];
    const float* pg  = (const float*)d_in[12];
    const float* pbt = (const float*)d_in[13];
    const float* pm  = (const float*)d_in[14];
    const float* pv  = (const float*)d_in[15];
    const float* pw2 = (const float*)d_in[16];
    const float* pb2 = (const float*)d_in[17];
    const float* aw1 = (const float*)d_in[18];
    const float* ab1 = (const float*)d_in[19];
    const float* ag  = (const float*)d_in[20];
    const float* abt2= (const float*)d_in[21];
    const float* am  = (const float*)d_in[22];
    const float* av  = (const float*)d_in[23];
    const float* awt = (const float*)d_in[24];
    const float* abt = (const float*)d_in[25];
    const float* we  = (const float*)d_in[26];
    const float* be  = (const float*)d_in[27];
    float* out = (float*)d_out;

    prep_kernel<<<64, 256>>>(aw1, pw2);
    qkv_kernel<<<dim3(NPTS / 64, BATCH), 256>>>(query, key_feat, wq, bq, wk, bk, wv, bv);
    knn_kernel<<<dim3(NPTS / 256, BATCH), 256>>>(pos1, pos2);
    attn_kernel<<<dim3(NPTS, BATCH), 256>>>(
        pos1, pos2, query,
        pw1, pb1, pg, pbt, pm, pv, pb2,
        ab1, ag, abt2, am, av, awt, abt, we, be, out);
}

// round 3
// speedup vs baseline: 1.6390x; 1.3433x over previous
#include <cuda_runtime.h>
#include <math.h>

#define BATCH 4
#define NPTS 4096
#define NPTS2 4096
#define CINC 128
#define DIMC 64
#define KNNC 20
#define UPF 2
#define HPOSC 64
#define HATTC 256
#define EPSV 1e-5f
#define PPB 2          // points per block in attn

// ---------------- scratch (static device memory; no allocations) ----------------
__device__ float g_qt[BATCH * NPTS * DIMC];   // (b, n, o) point-major
__device__ float g_kt[BATCH * NPTS2 * DIMC];
__device__ float g_vt[BATCH * NPTS2 * DIMC];
__device__ int   g_idx[BATCH * NPTS * KNNC];
__device__ float g_aw1p[DIMC * HATTC];        // paired: [o][2c']=(aw1[c'][o], aw1[c'+128][o])
__device__ float g_pw2t[HPOSC * DIMC];        // pw2 transposed: [h][o]

// ---------------- packed f32x2 helpers ----------------
__device__ __forceinline__ unsigned long long ffma2(
    unsigned long long a, unsigned long long b, unsigned long long c) {
    unsigned long long d;
    asm("fma.rn.f32x2 %0, %1, %2, %3;" : "=l"(d) : "l"(a), "l"(b), "l"(c));
    return d;
}
__device__ __forceinline__ unsigned long long pack2(float lo, float hi) {
    unsigned long long d;
    asm("mov.b64 %0, {%1, %2};" : "=l"(d) : "f"(lo), "f"(hi));
    return d;
}
__device__ __forceinline__ void unpack2(unsigned long long v, float& lo, float& hi) {
    asm("mov.b64 {%0, %1}, %2;" : "=f"(lo), "=f"(hi) : "l"(v));
}

// ================= prep: transpose/pair small weights =================
__global__ __launch_bounds__(256) void prep_kernel(
    const float* __restrict__ aw1, const float* __restrict__ pw2)
{
    int i = blockIdx.x * 256 + threadIdx.x;
    if (i < DIMC * 128) {              // pair aw1 columns c and c+128
        int o = i >> 7, c = i & 127;
        g_aw1p[o * HATTC + 2 * c]     = aw1[c * DIMC + o];
        g_aw1p[o * HATTC + 2 * c + 1] = aw1[(c + 128) * DIMC + o];
    }
    if (i < DIMC * HPOSC) {            // pw2[o][h] -> g_pw2t[h][o]
        int o = i >> 6, h = i & 63;
        g_pw2t[h * DIMC + o] = pw2[i];
    }
}

// ================= QKV projection kernel =================
__global__ __launch_bounds__(256) void qkv_kernel(
    const float* __restrict__ query, const float* __restrict__ key_feat,
    const float* __restrict__ wq, const float* __restrict__ bq,
    const float* __restrict__ wk, const float* __restrict__ bk,
    const float* __restrict__ wv, const float* __restrict__ bv)
{
    int b = blockIdx.y;
    int n0 = blockIdx.x * 64;
    int tid = threadIdx.x;
    __shared__ float tile[CINC * 64];

    for (int i = tid; i < CINC * 64; i += 256) {
        int c = i >> 6, j = i & 63;
        tile[i] = query[(b * CINC + c) * NPTS + n0 + j];
    }
    __syncthreads();
    int o = tid & 63;
    int jb = tid >> 6;  // 0..3
    {
        float acc[16];
#pragma unroll
        for (int i = 0; i < 16; i++) acc[i] = 0.f;
        const float4* w4 = reinterpret_cast<const float4*>(wq + o * CINC);
        for (int c4 = 0; c4 < CINC / 4; c4++) {
            float4 w = w4[c4];
#pragma unroll
            for (int j = 0; j < 4; j++) {
                float wj = (j == 0) ? w.x : (j == 1) ? w.y : (j == 2) ? w.z : w.w;
                const float* tp = tile + (c4 * 4 + j) * 64 + jb;
#pragma unroll
                for (int i = 0; i < 16; i++)
                    acc[i] = fmaf(wj, tp[4 * i], acc[i]);
            }
        }
        float bias = bq[o];
#pragma unroll
        for (int i = 0; i < 16; i++)
            g_qt[(b * NPTS + n0 + jb + 4 * i) * DIMC + o] = acc[i] + bias;
    }
    __syncthreads();
    for (int i = tid; i < CINC * 64; i += 256) {
        int c = i >> 6, j = i & 63;
        tile[i] = key_feat[(b * CINC + c) * NPTS2 + n0 + j];
    }
    __syncthreads();
    {
        float acck[16], accv[16];
#pragma unroll
        for (int i = 0; i < 16; i++) { acck[i] = 0.f; accv[i] = 0.f; }
        const float4* wk4 = reinterpret_cast<const float4*>(wk + o * CINC);
        const float4* wv4 = reinterpret_cast<const float4*>(wv + o * CINC);
        for (int c4 = 0; c4 < CINC / 4; c4++) {
            float4 wa = wk4[c4];
            float4 wb = wv4[c4];
#pragma unroll
            for (int j = 0; j < 4; j++) {
                float wkk = (j == 0) ? wa.x : (j == 1) ? wa.y : (j == 2) ? wa.z : wa.w;
                float wvv = (j == 0) ? wb.x : (j == 1) ? wb.y : (j == 2) ? wb.z : wb.w;
                const float* tp = tile + (c4 * 4 + j) * 64 + jb;
#pragma unroll
                for (int i = 0; i < 16; i++) {
                    float t = tp[4 * i];
                    acck[i] = fmaf(wkk, t, acck[i]);
                    accv[i] = fmaf(wvv, t, accv[i]);
                }
            }
        }
        float bkk = bk[o], bvv = bv[o];
#pragma unroll
        for (int i = 0; i < 16; i++) {
            int nn = n0 + jb + 4 * i;
            g_kt[(b * NPTS2 + nn) * DIMC + o] = acck[i] + bkk;
            g_vt[(b * NPTS2 + nn) * DIMC + o] = accv[i] + bvv;
        }
    }
}

// ================= KNN kernel =================
__global__ __launch_bounds__(256) void knn_kernel(
    const float* __restrict__ pos1, const float* __restrict__ pos2)
{
    int b = blockIdx.y;
    int tid = threadIdx.x;
    int n = blockIdx.x * 256 + tid;
    __shared__ float sx[2048], sy[2048], sz[2048], sn[2048];

    float qx = pos1[(b * 3 + 0) * NPTS + n];
    float qy = pos1[(b * 3 + 1) * NPTS + n];
    float qz = pos1[(b * 3 + 2) * NPTS + n];
    float n1 = qx * qx + qy * qy + qz * qz;

    float bd[KNNC];
    int bi[KNNC];
#pragma unroll
    for (int j = 0; j < KNNC; j++) { bd[j] = 3.4e38f; bi[j] = 0; }

    for (int chunk = 0; chunk < 2; chunk++) {
        int base = chunk * 2048;
        __syncthreads();
        for (int i = tid; i < 2048; i += 256) {
            float x = pos2[(b * 3 + 0) * NPTS2 + base + i];
            float y = pos2[(b * 3 + 1) * NPTS2 + base + i];
            float z = pos2[(b * 3 + 2) * NPTS2 + base + i];
            sx[i] = x; sy[i] = y; sz[i] = z;
            sn[i] = x * x + y * y + z * z;
        }
        __syncthreads();
#pragma unroll 4
        for (int m = 0; m < 2048; m++) {
            float dot = fmaf(qx, sx[m], fmaf(qy, sy[m], qz * sz[m]));
            float d = n1 + sn[m] - 2.f * dot;
            if (d < bd[KNNC - 1]) {
                float cd = d; int ci = base + m;
#pragma unroll
                for (int j = 0; j < KNNC; j++) {
                    if (cd < bd[j]) {
                        float td = bd[j]; bd[j] = cd; cd = td;
                        int ti = bi[j]; bi[j] = ci; ci = ti;
                    }
                }
            }
        }
    }
#pragma unroll
    for (int j = 0; j < KNNC; j++) g_idx[(n + b * NPTS) * KNNC + j] = bi[j];
}

// ================= Fused per-point attention kernel =================
// grid (N/PPB, B), block 256. PPB points per block.
__global__ __launch_bounds__(256) void attn_kernel(
    const float* __restrict__ pos1, const float* __restrict__ pos2,
    const float* __restrict__ query,
    const float* __restrict__ pw1, const float* __restrict__ pb1,
    const float* __restrict__ pg,  const float* __restrict__ pbt,
    const float* __restrict__ pm,  const float* __restrict__ pv,
    const float* __restrict__ pb2,
    const float* __restrict__ ab1,
    const float* __restrict__ ag,  const float* __restrict__ abt2,
    const float* __restrict__ am,  const float* __restrict__ av,
    const float* __restrict__ awt, const float* __restrict__ abt,
    const float* __restrict__ we,  const float* __restrict__ be,
    float* __restrict__ out)
{
    int b = blockIdx.y;
    int n0 = blockIdx.x * PPB;
    int tid = threadIdx.x;

    __shared__ __align__(16) float s_h[PPB * DIMC * KNNC];    // rows stride 20
    __shared__ __align__(16) float s_vg[PPB * DIMC * KNNC];
    __shared__ __align__(16) float s_a[PPB * HATTC * KNNC];   // also reused as phase-3 partial buf
    __shared__ __align__(16) float s_pe1[PPB * HPOSC * 24];   // k padded to 24
    __shared__ float s_q[PPB * DIMC];
    __shared__ float s_prel[PPB * 3 * KNNC];
    __shared__ float s_agg[PPB * DIMC * UPF];
    __shared__ int   s_idx[PPB * KNNC];

    // ---- Phase 0: load idx, q, pos_rel, gathers ----
    if (tid < PPB * KNNC) {
        int p = tid / KNNC, k = tid - p * KNNC;
        s_idx[tid] = g_idx[(b * NPTS + n0 + p) * KNNC + k];
    }
    if (tid < PPB * DIMC) {
        int p = tid >> 6, o = tid & 63;
        s_q[tid] = g_qt[(b * NPTS + n0 + p) * DIMC + o];
    }
    __syncthreads();

    if (tid < PPB * 3 * KNNC) {
        int p = tid / (3 * KNNC), rem = tid - p * 3 * KNNC;
        int c = rem / KNNC, k = rem - c * KNNC;
        s_prel[tid] = pos1[(b * 3 + c) * NPTS + n0 + p]
                    - pos2[(b * 3 + c) * NPTS2 + s_idx[p * KNNC + k]];
    }
#pragma unroll
    for (int p = 0; p < PPB; p++) {
        for (int e = tid; e < DIMC * KNNC; e += 256) {
            int k = e >> 6, o = e & 63;
            int m = s_idx[p * KNNC + k];
            s_h[p * DIMC * KNNC + o * KNNC + k]  = s_q[p * DIMC + o] - g_kt[(b * NPTS2 + m) * DIMC + o];
            s_vg[p * DIMC * KNNC + o * KNNC + k] = g_vt[(b * NPTS2 + m) * DIMC + o];
        }
    }
    __syncthreads();

    // ---- Phase 1: pos mlp layer 1 (3->64) + BN + ReLU into s_pe1 ----
#pragma unroll
    for (int p = 0; p < PPB; p++) {
        for (int e = tid; e < HPOSC * 24; e += 256) {
            int h = e / 24, k = e - h * 24;
            float val = 0.f;
            if (k < KNNC) {
                const float* pr = s_prel + p * 3 * KNNC;
                float acc = fmaf(pw1[h * 3 + 0], pr[k],
                            fmaf(pw1[h * 3 + 1], pr[KNNC + k],
                                 pw1[h * 3 + 2] * pr[2 * KNNC + k])) + pb1[h];
                float inv = pg[h] * rsqrtf(pv[h] + EPSV);
                acc = fmaf(acc, inv, pbt[h] - pm[h] * inv);
                val = fmaxf(acc, 0.f);
            }
            s_pe1[p * HPOSC * 24 + e] = val;
        }
    }
    __syncthreads();

    // ---- Phase 1b: pos mlp layer 2 (64->64), f32x2 over channel pairs ----
#pragma unroll
    for (int p = 0; p < PPB; p++) {
        int op = tid & 31, kg = tid >> 5;   // 8 groups x 3 k
        int o0 = op * 2, k0 = kg * 3;
        unsigned long long acc[3] = {0ULL, 0ULL, 0ULL};
#pragma unroll 4
        for (int h = 0; h < HPOSC; h++) {
            unsigned long long w2 =
                *reinterpret_cast<const unsigned long long*>(g_pw2t + h * DIMC + o0);
            const float* br = s_pe1 + p * HPOSC * 24 + h * 24 + k0;
            acc[0] = ffma2(w2, pack2(br[0], br[0]), acc[0]);
            acc[1] = ffma2(w2, pack2(br[1], br[1]), acc[1]);
            acc[2] = ffma2(w2, pack2(br[2], br[2]), acc[2]);
        }
        float b0 = pb2[o0], b1 = pb2[o0 + 1];
        float* hb = s_h + p * DIMC * KNNC;
        float* vb = s_vg + p * DIMC * KNNC;
#pragma unroll
        for (int j = 0; j < 3; j++) {
            int k = k0 + j;
            if (k < KNNC) {
                float lo, hi;
                unpack2(acc[j], lo, hi);
                float v0 = lo + b0, v1 = hi + b1;
                hb[o0 * KNNC + k] += v0;
                vb[o0 * KNNC + k] += v0;
                hb[(o0 + 1) * KNNC + k] += v1;
                vb[(o0 + 1) * KNNC + k] += v1;
            }
        }
    }
    __syncthreads();

    // ---- Phase 2: a = relu(bn(aw1 @ h)); thread = (point, c); computes c and c+128 ----
    {
        int c = tid & 127, p = tid >> 7;
        unsigned long long acc[2][10];
#pragma unroll
        for (int j = 0; j < 10; j++) { acc[0][j] = 0ULL; acc[1][j] = 0ULL; }
        const float* hb = s_h + p * DIMC * KNNC;
#pragma unroll 4
        for (int o = 0; o < DIMC; o++) {
            unsigned long long wpair =
                *reinterpret_cast<const unsigned long long*>(g_aw1p + o * HATTC + 2 * c);
            float w0, w1;
            unpack2(wpair, w0, w1);
            unsigned long long wp0 = pack2(w0, w0);
            unsigned long long wp1 = pack2(w1, w1);
            const ulonglong2* hr = reinterpret_cast<const ulonglong2*>(hb + o * KNNC);
#pragma unroll
            for (int j = 0; j < 5; j++) {
                ulonglong2 hv = hr[j];
                acc[0][2 * j]     = ffma2(wp0, hv.x, acc[0][2 * j]);
                acc[0][2 * j + 1] = ffma2(wp0, hv.y, acc[0][2 * j + 1]);
                acc[1][2 * j]     = ffma2(wp1, hv.x, acc[1][2 * j]);
                acc[1][2 * j + 1] = ffma2(wp1, hv.y, acc[1][2 * j + 1]);
            }
        }
#pragma unroll
        for (int cc = 0; cc < 2; cc++) {
            int cg = c + cc * 128;
            float inv = ag[cg] * rsqrtf(av[cg] + EPSV);
            float bias = fmaf(ab1[cg], inv, abt2[cg]) - am[cg] * inv;
            unsigned long long* row =
                reinterpret_cast<unsigned long long*>(s_a + p * HATTC * KNNC + cg * KNNC);
#pragma unroll
            for (int j = 0; j < 10; j++) {
                float lo, hi;
                unpack2(acc[cc][j], lo, hi);
                lo = fmaxf(fmaf(lo, inv, bias), 0.f);
                hi = fmaxf(fmaf(hi, inv, bias), 0.f);
                row[j] = pack2(lo, hi);
            }
        }
    }
    __syncthreads();

    // ---- Phase 3: att partial = awt^T @ a; thread = (rowpair t, chalf, point) ----
    int t = tid & 63;               // rows 2t, 2t+1
    int chalf = (tid >> 6) & 1;     // channel half
    int p3 = tid >> 7;              // point
    unsigned long long acc3[2][10];
    {
#pragma unroll
        for (int j = 0; j < 10; j++) { acc3[0][j] = 0ULL; acc3[1][j] = 0ULL; }
        const float* wb = awt + (chalf * 128) * (DIMC * UPF) + 2 * t;
        const float* ab = s_a + p3 * HATTC * KNNC + (chalf * 128) * KNNC;
#pragma unroll 4
        for (int cc = 0; cc < 128; cc++) {
            float2 w2 = *reinterpret_cast<const float2*>(wb + cc * (DIMC * UPF));
            unsigned long long wp0 = pack2(w2.x, w2.x);
            unsigned long long wp1 = pack2(w2.y, w2.y);
            const ulonglong2* ar = reinterpret_cast<const ulonglong2*>(ab + cc * KNNC);
#pragma unroll
            for (int j = 0; j < 5; j++) {
                ulonglong2 av2 = ar[j];
                acc3[0][2 * j]     = ffma2(wp0, av2.x, acc3[0][2 * j]);
                acc3[0][2 * j + 1] = ffma2(wp0, av2.y, acc3[0][2 * j + 1]);
                acc3[1][2 * j]     = ffma2(wp1, av2.x, acc3[1][2 * j]);
                acc3[1][2 * j + 1] = ffma2(wp1, av2.y, acc3[1][2 * j + 1]);
            }
        }
    }
    __syncthreads();   // all s_a reads done; safe to reuse as partial buffer
    if (chalf) {
        unsigned long long* dst =
            reinterpret_cast<unsigned long long*>(s_a + p3 * HATTC * KNNC) + t * 20;
#pragma unroll
        for (int j = 0; j < 10; j++) { dst[j] = acc3[0][j]; dst[10 + j] = acc3[1][j]; }
    }
    __syncthreads();

    // ---- Phase 4: combine halves, softmax over K, weighted sum with vg ----
    if (!chalf) {
        float ab = abt[t];
        const unsigned long long* part =
            reinterpret_cast<const unsigned long long*>(s_a + p3 * HATTC * KNNC) + t * 20;
        float vr[KNNC];
        {
            const float4* vgr = reinterpret_cast<const float4*>(s_vg + p3 * DIMC * KNNC + t * KNNC);
#pragma unroll
            for (int j = 0; j < 5; j++) {
                float4 v4 = vgr[j];
                vr[4 * j] = v4.x; vr[4 * j + 1] = v4.y; vr[4 * j + 2] = v4.z; vr[4 * j + 3] = v4.w;
            }
        }
#pragma unroll
        for (int r = 0; r < 2; r++) {
            float vals[KNNC];
            float mx = -3.4e38f;
#pragma unroll
            for (int j = 0; j < 10; j++) {
                float lo, hi, plo, phi;
                unpack2(acc3[r][j], lo, hi);
                unpack2(part[r * 10 + j], plo, phi);
                float t0 = lo + plo + ab;
                float t1 = hi + phi + ab;
                vals[2 * j] = t0;
                vals[2 * j + 1] = t1;
                mx = fmaxf(mx, fmaxf(t0, t1));
            }
            float s = 0.f, wsum = 0.f;
#pragma unroll
            for (int k = 0; k < KNNC; k++) {
                float e = expf(vals[k] - mx);
                s += e;
                wsum = fmaf(e, vr[k], wsum);
            }
            s_agg[p3 * DIMC * UPF + t * 2 + r] = wsum / s;
        }
    }
    __syncthreads();

    // ---- Phase 5: y = we @ agg + be + residual ----
    {
        int c2 = tid >> 1, r = tid & 1;
        float accp[PPB];
#pragma unroll
        for (int p = 0; p < PPB; p++) accp[p] = 0.f;
        const float4* w4 = reinterpret_cast<const float4*>(we + c2 * DIMC);
#pragma unroll 4
        for (int o4 = 0; o4 < DIMC / 4; o4++) {
            float4 w = w4[o4];
#pragma unroll
            for (int j = 0; j < 4; j++) {
                float wj = (j == 0) ? w.x : (j == 1) ? w.y : (j == 2) ? w.z : w.w;
                int o = o4 * 4 + j;
#pragma unroll
                for (int p = 0; p < PPB; p++)
                    accp[p] = fmaf(wj, s_agg[p * DIMC * UPF + o * UPF + r], accp[p]);
            }
        }
        float bb = be[c2];
#pragma unroll
        for (int p = 0; p < PPB; p++) {
            out[((size_t)(b * CINC + c2)) * (NPTS * UPF) + 2 * (size_t)(n0 + p) + r] =
                accp[p] + bb + query[(b * CINC + c2) * NPTS + n0 + p];
        }
    }
}

// ================= launch =================
extern "C" void kernel_launch(void* const* d_in, const int* in_sizes, int n_in,
                              void* d_out, int out_size)
{
    const float* pos1     = (const float*)d_in[0];
    const float* query    = (const float*)d_in[1];
    const float* pos2     = (const float*)d_in[2];
    const float* key_feat = (const float*)d_in[3];
    const float* wq  = (const float*)d_in[4];
    const float* bq  = (const float*)d_in[5];
    const float* wk  = (const float*)d_in[6];
    const float* bk  = (const float*)d_in[7];
    const float* wv  = (const float*)d_in[8];
    const float* bv  = (const float*)d_in[9];
    const float* pw1 = (const float*)d_in[10];
    const float* pb1 = (const float*)d_in[11];
    const float* pg  = (const float*)d_in[12];
    const float* pbt = (const float*)d_in[13];
    const float* pm  = (const float*)d_in[14];
    const float* pv  = (const float*)d_in[15];
    const float* pw2 = (const float*)d_in[16];
    const float* pb2 = (const float*)d_in[17];
    const float* aw1 = (const float*)d_in[18];
    const float* ab1 = (const float*)d_in[19];
    const float* ag  = (const float*)d_in[20];
    const float* abt2= (const float*)d_in[21];
    const float* am  = (const float*)d_in[22];
    const float* av  = (const float*)d_in[23];
    const float* awt = (const float*)d_in[24];
    const float* abt = (const float*)d_in[25];
    const float* we  = (const float*)d_in[26];
    const float* be  = (const float*)d_in[27];
    float* out = (float*)d_out;

    prep_kernel<<<64, 256>>>(aw1, pw2);
    qkv_kernel<<<dim3(NPTS / 64, BATCH), 256>>>(query, key_feat, wq, bq, wk, bk, wv, bv);
    knn_kernel<<<dim3(NPTS / 256, BATCH), 256>>>(pos1, pos2);
    attn_kernel<<<dim3(NPTS / PPB, BATCH), 256>>>(
        pos1, pos2, query,
        pw1, pb1, pg, pbt, pm, pv, pb2,
        ab1, ag, abt2, am, av, awt, abt, we, be, out);
}